// round 1
// baseline (speedup 1.0000x reference)
#include <cuda_runtime.h>
#include <cuda_bf16.h>
#include <math.h>

// ---------------------------------------------------------------------------
// DiT block, fp32, f32x2-packed SIMT math (B300 fp32 3-reg FFMA is half rate;
// fma.rn.f32x2 restores full rate). Pipeline:
//   mod  = silu(c) @ w_ada + b_ada
//   h    = LN(x)*(1+g1)+be1
//   qkv  = h @ w_qkv + b_qkv
//   attn = softmax(q k^T / 8) v        (flash-style, per-head)
//   x1   = x + a1*(attn @ w_proj + b_proj)
//   h    = LN(x1)*(1+g2)+be2
//   mlp  = gelu(h @ w_mlp1 + b_mlp1)
//   out  = x1 + a2*(mlp @ w_mlp2 + b_mlp2)
// ---------------------------------------------------------------------------

typedef unsigned long long ull;

#define DIM 1024
#define MODW 6144
#define TOKENS 8192   // B(8) * N(1024)

__device__ __forceinline__ void fma2(ull& d, ull a, ull b) {
    asm("fma.rn.f32x2 %0, %1, %2, %0;" : "+l"(d) : "l"(a), "l"(b));
}
__device__ __forceinline__ ull mul2(ull a, ull b) {
    ull r; asm("mul.rn.f32x2 %0, %1, %2;" : "=l"(r) : "l"(a), "l"(b)); return r;
}
__device__ __forceinline__ ull pack2(float lo, float hi) {
    ull r; asm("mov.b64 %0, {%1, %2};" : "=l"(r) : "f"(lo), "f"(hi)); return r;
}
__device__ __forceinline__ void unpack2(ull v, float& lo, float& hi) {
    asm("mov.b64 {%0, %1}, %2;" : "=f"(lo), "=f"(hi) : "l"(v));
}

// ------------------------- scratch (no allocations allowed) ----------------
__device__ float g_mod[8 * MODW];
__device__ float g_h[(size_t)TOKENS * DIM];
__device__ float g_qkv[(size_t)TOKENS * 3 * DIM];
__device__ float g_attn[(size_t)TOKENS * DIM];
__device__ float g_x1[(size_t)TOKENS * DIM];
__device__ float g_mlp[(size_t)TOKENS * 4 * DIM];

// ------------------------- adaLN modulation GEMM ---------------------------
// mod[b, col] = sum_k silu(c[b,k]) * w_ada[k,col] + b_ada[col]
// grid 24 blocks x 256 threads: each thread owns one of 6144 columns, all 8 rows.
__global__ __launch_bounds__(256) void ada_kernel(
    const float* __restrict__ c, const float* __restrict__ w,
    const float* __restrict__ bias, float* __restrict__ mod)
{
    __shared__ float sc[8 * DIM];
    const int tid = threadIdx.x;
    for (int i = tid; i < 8 * DIM; i += 256) {
        float v = c[i];
        sc[i] = v / (1.f + __expf(-v));
    }
    __syncthreads();
    const int col = blockIdx.x * 256 + tid;
    float acc[8];
    #pragma unroll
    for (int b = 0; b < 8; b++) acc[b] = 0.f;
    for (int k = 0; k < DIM; k++) {
        float wv = w[k * MODW + col];
        #pragma unroll
        for (int b = 0; b < 8; b++) acc[b] = fmaf(sc[b * DIM + k], wv, acc[b]);
    }
    float bv = bias[col];
    #pragma unroll
    for (int b = 0; b < 8; b++) mod[b * MODW + col] = acc[b] + bv;
}

// ------------------------- LayerNorm + modulate -----------------------------
// h = (x - mu)/sqrt(var+eps) * (1 + mod[g_off]) + mod[b_off]
__global__ __launch_bounds__(256) void ln_mod_kernel(
    const float* __restrict__ x, const float* __restrict__ mod,
    float* __restrict__ h, int g_off, int b_off)
{
    __shared__ float s_sum[8], s_sq[8], s_stats[2];
    const int token = blockIdx.x;
    const int batch = token >> 10;
    const int tid = threadIdx.x;

    const float4* xp = (const float4*)(x + (size_t)token * DIM);
    float4 v = xp[tid];
    float sum = v.x + v.y + v.z + v.w;
    float sq  = v.x*v.x + v.y*v.y + v.z*v.z + v.w*v.w;
    #pragma unroll
    for (int o = 16; o > 0; o >>= 1) {
        sum += __shfl_xor_sync(0xffffffffu, sum, o);
        sq  += __shfl_xor_sync(0xffffffffu, sq,  o);
    }
    if ((tid & 31) == 0) { s_sum[tid >> 5] = sum; s_sq[tid >> 5] = sq; }
    __syncthreads();
    if (tid < 32) {
        float a = (tid < 8) ? s_sum[tid] : 0.f;
        float b = (tid < 8) ? s_sq[tid]  : 0.f;
        #pragma unroll
        for (int o = 4; o > 0; o >>= 1) {
            a += __shfl_xor_sync(0xffffffffu, a, o);
            b += __shfl_xor_sync(0xffffffffu, b, o);
        }
        if (tid == 0) {
            float mu = a * (1.f / DIM);
            float var = b * (1.f / DIM) - mu * mu;
            s_stats[0] = mu;
            s_stats[1] = rsqrtf(var + 1e-6f);
        }
    }
    __syncthreads();
    const float mu = s_stats[0], rstd = s_stats[1];
    const float4* gp = (const float4*)(mod + batch * MODW + g_off);
    const float4* bp = (const float4*)(mod + batch * MODW + b_off);
    float4 g = gp[tid], be = bp[tid], o;
    o.x = (v.x - mu) * rstd * (1.f + g.x) + be.x;
    o.y = (v.y - mu) * rstd * (1.f + g.y) + be.y;
    o.z = (v.z - mu) * rstd * (1.f + g.z) + be.z;
    o.w = (v.w - mu) * rstd * (1.f + g.w) + be.w;
    ((float4*)(h + (size_t)token * DIM))[tid] = o;
}

// ------------------------- tiled GEMM, f32x2 inner -------------------------
// C[M,N] = A[M,K] @ B[K,N] (+ epilogue). 128x128x16 tile, 256 thr, 8x8/thread.
// EPI 0: C = v + bias
// EPI 1: C = gelu(v + bias)            (exact, erf)
// EPI 2: C = res + mod[batch, mod_off + col] * (v + bias)
#define BM 128
#define BN 128
#define BKT 16

__device__ __forceinline__ float gelu_exact(float v) {
    return 0.5f * v * (1.f + erff(v * 0.70710678118654752f));
}

template<int EPI>
__global__ __launch_bounds__(256, 2) void gemm_f32x2(
    const float* __restrict__ A, const float* __restrict__ B,
    const float* __restrict__ bias, float* __restrict__ C,
    int M, int N, int K,
    const float* __restrict__ res, const float* __restrict__ mod, int mod_off)
{
    __shared__ __align__(16) float As[BKT][BM];
    __shared__ __align__(16) float Bs[BKT][BN];

    const int tid = threadIdx.x;
    const int tx = tid & 15;
    const int ty = tid >> 4;
    const int row0 = blockIdx.y * BM;
    const int col0 = blockIdx.x * BN;

    const int a_r  = tid >> 2;   // 0..63 (+64)
    const int a_c4 = tid & 3;    // float4 index within BK
    const int b_r  = tid >> 5;   // 0..7 (+8)
    const int b_c4 = tid & 31;   // float4 index within BN

    ull acc[8][4];
    #pragma unroll
    for (int i = 0; i < 8; i++)
        #pragma unroll
        for (int j = 0; j < 4; j++) acc[i][j] = 0ULL;

    const float* Aptr = A + (size_t)row0 * K;
    const float* Bptr = B + col0;

    for (int kt = 0; kt < K; kt += BKT) {
        #pragma unroll
        for (int p = 0; p < 2; p++) {
            int r = a_r + p * 64;
            float4 v = *(const float4*)(Aptr + (size_t)r * K + kt + a_c4 * 4);
            As[a_c4 * 4 + 0][r] = v.x;
            As[a_c4 * 4 + 1][r] = v.y;
            As[a_c4 * 4 + 2][r] = v.z;
            As[a_c4 * 4 + 3][r] = v.w;
        }
        #pragma unroll
        for (int p = 0; p < 2; p++) {
            int r = b_r + p * 8;
            *(float4*)(&Bs[r][b_c4 * 4]) =
                *(const float4*)(Bptr + (size_t)(kt + r) * N + b_c4 * 4);
        }
        __syncthreads();
        #pragma unroll
        for (int k = 0; k < BKT; k++) {
            float4 a0 = *(const float4*)(&As[k][ty * 8]);
            float4 a1 = *(const float4*)(&As[k][ty * 8 + 4]);
            float4 b0 = *(const float4*)(&Bs[k][tx * 8]);
            float4 b1 = *(const float4*)(&Bs[k][tx * 8 + 4]);
            ull b2[4] = { pack2(b0.x, b0.y), pack2(b0.z, b0.w),
                          pack2(b1.x, b1.y), pack2(b1.z, b1.w) };
            float av[8] = {a0.x, a0.y, a0.z, a0.w, a1.x, a1.y, a1.z, a1.w};
            #pragma unroll
            for (int i = 0; i < 8; i++) {
                ull a2 = pack2(av[i], av[i]);
                #pragma unroll
                for (int j = 0; j < 4; j++) fma2(acc[i][j], a2, b2[j]);
            }
        }
        __syncthreads();
    }

    #pragma unroll
    for (int i = 0; i < 8; i++) {
        int row = row0 + ty * 8 + i;
        int batch = row >> 10;
        #pragma unroll
        for (int j = 0; j < 4; j++) {
            int col = col0 + tx * 8 + j * 2;
            float lo, hi;
            unpack2(acc[i][j], lo, hi);
            float v0 = lo + bias[col];
            float v1 = hi + bias[col + 1];
            if (EPI == 1) { v0 = gelu_exact(v0); v1 = gelu_exact(v1); }
            if (EPI == 2) {
                float m0 = mod[batch * MODW + mod_off + col];
                float m1 = mod[batch * MODW + mod_off + col + 1];
                v0 = res[(size_t)row * N + col]     + m0 * v0;
                v1 = res[(size_t)row * N + col + 1] + m1 * v1;
            }
            C[(size_t)row * N + col]     = v0;
            C[(size_t)row * N + col + 1] = v1;
        }
    }
}

// ------------------------- attention (flash-style) -------------------------
// grid (4 q-tiles, 16 heads, 8 batch), 256 threads; one q row per thread.
// KV tiles of 32 rows staged in smem; online softmax; f32x2 dots + PV.
__global__ __launch_bounds__(256, 1) void attn_kernel(
    const float* __restrict__ qkv, float* __restrict__ out)
{
    __shared__ __align__(16) float ks[32 * 64];
    __shared__ __align__(16) float vs[32 * 64];

    const int tid = threadIdx.x;
    const int head = blockIdx.y;
    const int batch = blockIdx.z;
    const int qrow = blockIdx.x * 256 + tid;
    const size_t token = (size_t)batch * 1024 + qrow;

    const float* qp = qkv + token * 3072 + head * 64;
    ull q2[32];
    #pragma unroll
    for (int i = 0; i < 16; i++) {
        float4 v = *(const float4*)(qp + i * 4);
        q2[2 * i]     = pack2(v.x * 0.125f, v.y * 0.125f);
        q2[2 * i + 1] = pack2(v.z * 0.125f, v.w * 0.125f);
    }
    ull o2[32];
    #pragma unroll
    for (int i = 0; i < 32; i++) o2[i] = 0ULL;
    float m = -1e30f, l = 0.f;
    float s[32];

    const float* kbase = qkv + (size_t)batch * 1024 * 3072 + 1024 + head * 64;

    for (int t = 0; t < 32; t++) {
        __syncthreads();
        #pragma unroll
        for (int p = 0; p < 2; p++) {
            int f = tid + p * 256;          // 0..511
            int kr = f >> 4, d4 = f & 15;
            const float* src = kbase + (size_t)(t * 32 + kr) * 3072 + d4 * 4;
            *(float4*)(ks + kr * 64 + d4 * 4) = *(const float4*)src;
            *(float4*)(vs + kr * 64 + d4 * 4) = *(const float4*)(src + 1024);
        }
        __syncthreads();

        float tmax = m;
        #pragma unroll
        for (int kr = 0; kr < 32; kr++) {
            ull accA = 0ULL, accB = 0ULL;
            const ulonglong2* kp = (const ulonglong2*)(ks + kr * 64);
            #pragma unroll
            for (int i = 0; i < 16; i++) {
                ulonglong2 kk = kp[i];
                fma2(accA, q2[2 * i],     kk.x);
                fma2(accB, q2[2 * i + 1], kk.y);
            }
            float a0, a1, b0, b1;
            unpack2(accA, a0, a1);
            unpack2(accB, b0, b1);
            s[kr] = (a0 + a1) + (b0 + b1);
            tmax = fmaxf(tmax, s[kr]);
        }

        float alpha = __expf(m - tmax);
        m = tmax;
        l *= alpha;
        ull alpha2 = pack2(alpha, alpha);
        #pragma unroll
        for (int i = 0; i < 32; i++) o2[i] = mul2(o2[i], alpha2);

        #pragma unroll
        for (int kr = 0; kr < 32; kr++) {
            float p = __expf(s[kr] - m);
            l += p;
            ull p2 = pack2(p, p);
            const ulonglong2* vp = (const ulonglong2*)(vs + kr * 64);
            #pragma unroll
            for (int i = 0; i < 16; i++) {
                ulonglong2 vv = vp[i];
                fma2(o2[2 * i],     p2, vv.x);
                fma2(o2[2 * i + 1], p2, vv.y);
            }
        }
    }

    float inv = 1.f / l;
    float* op = out + token * 1024 + head * 64;
    #pragma unroll
    for (int i = 0; i < 16; i++) {
        float a0, a1, b0, b1;
        unpack2(o2[2 * i], a0, a1);
        unpack2(o2[2 * i + 1], b0, b1);
        float4 w = make_float4(a0 * inv, a1 * inv, b0 * inv, b1 * inv);
        *(float4*)(op + i * 4) = w;
    }
}

// ------------------------- launch -------------------------------------------
extern "C" void kernel_launch(void* const* d_in, const int* in_sizes, int n_in,
                              void* d_out, int out_size)
{
    (void)in_sizes; (void)n_in; (void)out_size;
    const float* x      = (const float*)d_in[0];
    const float* c      = (const float*)d_in[1];
    const float* w_qkv  = (const float*)d_in[2];
    const float* b_qkv  = (const float*)d_in[3];
    const float* w_proj = (const float*)d_in[4];
    const float* b_proj = (const float*)d_in[5];
    const float* w_mlp1 = (const float*)d_in[6];
    const float* b_mlp1 = (const float*)d_in[7];
    const float* w_mlp2 = (const float*)d_in[8];
    const float* b_mlp2 = (const float*)d_in[9];
    const float* w_ada  = (const float*)d_in[10];
    const float* b_ada  = (const float*)d_in[11];
    float* out = (float*)d_out;

    float *mod, *h, *qkvb, *attn, *x1, *mlp;
    cudaGetSymbolAddress((void**)&mod,  g_mod);
    cudaGetSymbolAddress((void**)&h,    g_h);
    cudaGetSymbolAddress((void**)&qkvb, g_qkv);
    cudaGetSymbolAddress((void**)&attn, g_attn);
    cudaGetSymbolAddress((void**)&x1,   g_x1);
    cudaGetSymbolAddress((void**)&mlp,  g_mlp);

    // 1) mod = silu(c) @ w_ada + b_ada
    ada_kernel<<<MODW / 256, 256>>>(c, w_ada, b_ada, mod);
    // 2) h = LN(x)*(1+g1)+be1
    ln_mod_kernel<<<TOKENS, 256>>>(x, mod, h, 0, DIM);
    // 3) qkv = h @ w_qkv + b_qkv
    gemm_f32x2<0><<<dim3(3 * DIM / BN, TOKENS / BM), 256>>>(
        h, w_qkv, b_qkv, qkvb, TOKENS, 3 * DIM, DIM, nullptr, nullptr, 0);
    // 4) attention
    attn_kernel<<<dim3(4, 16, 8), 256>>>(qkvb, attn);
    // 5) x1 = x + a1*(attn @ w_proj + b_proj)
    gemm_f32x2<2><<<dim3(DIM / BN, TOKENS / BM), 256>>>(
        attn, w_proj, b_proj, x1, TOKENS, DIM, DIM, x, mod, 2 * DIM);
    // 6) h = LN(x1)*(1+g2)+be2
    ln_mod_kernel<<<TOKENS, 256>>>(x1, mod, h, 3 * DIM, 4 * DIM);
    // 7) mlp = gelu(h @ w_mlp1 + b_mlp1)
    gemm_f32x2<1><<<dim3(4 * DIM / BN, TOKENS / BM), 256>>>(
        h, w_mlp1, b_mlp1, mlp, TOKENS, 4 * DIM, DIM, nullptr, nullptr, 0);
    // 8) out = x1 + a2*(mlp @ w_mlp2 + b_mlp2)
    gemm_f32x2<2><<<dim3(DIM / BN, TOKENS / BM), 256>>>(
        mlp, w_mlp2, b_mlp2, out, TOKENS, DIM, 4 * DIM, x1, mod, 5 * DIM);
}

// round 3
// speedup vs baseline: 1.9820x; 1.9820x over previous
#include <cuda_runtime.h>
#include <cuda_bf16.h>
#include <math.h>
#include <cstdint>

typedef unsigned long long ull;

#define DIM 1024
#define MODW 6144
#define TOKENS 8192   // B(8) * N(1024)

// ---------------------------------------------------------------------------
// f32x2 helpers (SIMT attention)
// ---------------------------------------------------------------------------
__device__ __forceinline__ void fma2(ull& d, ull a, ull b) {
    asm("fma.rn.f32x2 %0, %1, %2, %0;" : "+l"(d) : "l"(a), "l"(b));
}
__device__ __forceinline__ ull mul2(ull a, ull b) {
    ull r; asm("mul.rn.f32x2 %0, %1, %2;" : "=l"(r) : "l"(a), "l"(b)); return r;
}
__device__ __forceinline__ ull pack2(float lo, float hi) {
    ull r; asm("mov.b64 %0, {%1, %2};" : "=l"(r) : "f"(lo), "f"(hi)); return r;
}
__device__ __forceinline__ void unpack2(ull v, float& lo, float& hi) {
    asm("mov.b64 {%0, %1}, %2;" : "=f"(lo), "=f"(hi) : "l"(v));
}

// ---------------------------------------------------------------------------
// mma.sync / ldmatrix helpers (arch-generic tensor path; tcgen05 is gated off
// because the harness compiles PTX at target sm_103 without the 'a' feature)
// ---------------------------------------------------------------------------
__device__ __forceinline__ uint32_t smem_u32(const void* p) {
    uint32_t a;
    asm("{ .reg .u64 t; cvta.to.shared.u64 t, %1; cvt.u32.u64 %0, t; }"
        : "=r"(a) : "l"(p));
    return a;
}
__device__ __forceinline__ void ldsm4(uint32_t r[4], uint32_t addr) {
    asm volatile("ldmatrix.sync.aligned.m8n8.x4.shared.b16 {%0,%1,%2,%3}, [%4];"
        : "=r"(r[0]), "=r"(r[1]), "=r"(r[2]), "=r"(r[3]) : "r"(addr));
}
__device__ __forceinline__ void mma_bf16(float c[4], const uint32_t a[4],
                                         uint32_t b0, uint32_t b1) {
    asm volatile(
        "mma.sync.aligned.m16n8k16.row.col.f32.bf16.bf16.f32 "
        "{%0,%1,%2,%3}, {%4,%5,%6,%7}, {%8,%9}, {%0,%1,%2,%3};"
        : "+f"(c[0]), "+f"(c[1]), "+f"(c[2]), "+f"(c[3])
        : "r"(a[0]), "r"(a[1]), "r"(a[2]), "r"(a[3]), "r"(b0), "r"(b1));
}

// ---------------------------------------------------------------------------
// scratch (no allocations allowed)
// ---------------------------------------------------------------------------
__device__ float g_mod[8 * MODW];
__device__ float g_h[(size_t)TOKENS * DIM];
__device__ float g_qkv[(size_t)TOKENS * 3 * DIM];
__device__ float g_attn[(size_t)TOKENS * DIM];
__device__ float g_x1[(size_t)TOKENS * DIM];
__device__ float g_mlp[(size_t)TOKENS * 4 * DIM];
__device__ float g_wT[12 * 1024 * 1024 + 1024 * 1024];
#define O_QKVT 0
#define O_PROJT 3145728
#define O_MLP1T 4194304
#define O_MLP2T 8388608

// ---------------------------------------------------------------------------
// weight transpose: dst[c][r] = src[r][c], src is R x C
// ---------------------------------------------------------------------------
__global__ __launch_bounds__(256) void transpose_k(
    const float* __restrict__ s, float* __restrict__ d, int R, int C)
{
    __shared__ float t[32][33];
    const int bx = blockIdx.x * 32;
    const int by = blockIdx.y * 32;
    const int x = threadIdx.x, y = threadIdx.y;
    #pragma unroll
    for (int i = 0; i < 32; i += 8)
        t[y + i][x] = s[(size_t)(by + y + i) * C + bx + x];
    __syncthreads();
    #pragma unroll
    for (int i = 0; i < 32; i += 8)
        d[(size_t)(bx + y + i) * R + by + x] = t[x][y + i];
}

// ---------------------------------------------------------------------------
// adaLN modulation GEMM (M=8, SIMT)
// ---------------------------------------------------------------------------
__global__ __launch_bounds__(256) void ada_kernel(
    const float* __restrict__ c, const float* __restrict__ w,
    const float* __restrict__ bias, float* __restrict__ mod)
{
    __shared__ float sc[8 * DIM];
    const int tid = threadIdx.x;
    for (int i = tid; i < 8 * DIM; i += 256) {
        float v = c[i];
        sc[i] = v / (1.f + __expf(-v));
    }
    __syncthreads();
    const int col = blockIdx.x * 256 + tid;
    float acc[8];
    #pragma unroll
    for (int b = 0; b < 8; b++) acc[b] = 0.f;
    for (int k = 0; k < DIM; k++) {
        float wv = w[k * MODW + col];
        #pragma unroll
        for (int b = 0; b < 8; b++) acc[b] = fmaf(sc[b * DIM + k], wv, acc[b]);
    }
    float bv = bias[col];
    #pragma unroll
    for (int b = 0; b < 8; b++) mod[b * MODW + col] = acc[b] + bv;
}

// ---------------------------------------------------------------------------
// LayerNorm + modulate
// ---------------------------------------------------------------------------
__global__ __launch_bounds__(256) void ln_mod_kernel(
    const float* __restrict__ x, const float* __restrict__ mod,
    float* __restrict__ h, int g_off, int b_off)
{
    __shared__ float s_sum[8], s_sq[8], s_stats[2];
    const int token = blockIdx.x;
    const int batch = token >> 10;
    const int tid = threadIdx.x;

    const float4* xp = (const float4*)(x + (size_t)token * DIM);
    float4 v = xp[tid];
    float sum = v.x + v.y + v.z + v.w;
    float sq  = v.x*v.x + v.y*v.y + v.z*v.z + v.w*v.w;
    #pragma unroll
    for (int o = 16; o > 0; o >>= 1) {
        sum += __shfl_xor_sync(0xffffffffu, sum, o);
        sq  += __shfl_xor_sync(0xffffffffu, sq,  o);
    }
    if ((tid & 31) == 0) { s_sum[tid >> 5] = sum; s_sq[tid >> 5] = sq; }
    __syncthreads();
    if (tid < 32) {
        float a = (tid < 8) ? s_sum[tid] : 0.f;
        float b = (tid < 8) ? s_sq[tid]  : 0.f;
        #pragma unroll
        for (int o = 4; o > 0; o >>= 1) {
            a += __shfl_xor_sync(0xffffffffu, a, o);
            b += __shfl_xor_sync(0xffffffffu, b, o);
        }
        if (tid == 0) {
            float mu = a * (1.f / DIM);
            float var = b * (1.f / DIM) - mu * mu;
            s_stats[0] = mu;
            s_stats[1] = rsqrtf(var + 1e-6f);
        }
    }
    __syncthreads();
    const float mu = s_stats[0], rstd = s_stats[1];
    const float4* gp = (const float4*)(mod + batch * MODW + g_off);
    const float4* bp = (const float4*)(mod + batch * MODW + b_off);
    float4 g = gp[tid], be = bp[tid], o;
    o.x = (v.x - mu) * rstd * (1.f + g.x) + be.x;
    o.y = (v.y - mu) * rstd * (1.f + g.y) + be.y;
    o.z = (v.z - mu) * rstd * (1.f + g.z) + be.z;
    o.w = (v.w - mu) * rstd * (1.f + g.w) + be.w;
    ((float4*)(h + (size_t)token * DIM))[tid] = o;
}

// ---------------------------------------------------------------------------
// mma.sync GEMM: C[M,N] = A[M,K] @ Bt[N,K]^T, split-bf16 3-MMA fp32 emulation
// CTA tile 128x128, K-chunk 64, double-buffered bf16 hi/lo planes in smem.
// EPI 0: C = v + bias
// EPI 1: C = gelu(v + bias)            (exact, erf)
// EPI 2: C = res + mod[batch, mod_off+col] * (v + bias)
// ---------------------------------------------------------------------------
#define STG_A_HI 0
#define STG_A_LO 16384
#define STG_B_HI 32768
#define STG_B_LO 49152
#define STG_SIZE 65536
#define GEMM_SMEM (2 * STG_SIZE)   // 131072 B

// issue LDGs for a 128x64 fp32 tile (row stride ld)
__device__ __forceinline__ void ldg_tile(
    const float* __restrict__ g, int ld, int tid, float4 v[8])
{
    #pragma unroll
    for (int t = 0; t < 8; t++) {
        int idx = t * 256 + tid;
        v[t] = *(const float4*)(g + (size_t)(idx >> 4) * ld + (idx & 15) * 4);
    }
}

// split fp32 tile into bf16 hi/lo planes, store swizzled (SW128 pattern)
__device__ __forceinline__ void cvt_sts(
    char* hi, char* lo, int tid, const float4 v[8])
{
    #pragma unroll
    for (int t = 0; t < 8; t++) {
        int idx = t * 256 + tid;
        uint32_t h01, h23, l01, l23;
        asm("cvt.rn.bf16x2.f32 %0, %1, %2;" : "=r"(h01) : "f"(v[t].y), "f"(v[t].x));
        asm("cvt.rn.bf16x2.f32 %0, %1, %2;" : "=r"(h23) : "f"(v[t].w), "f"(v[t].z));
        float hx = __uint_as_float(h01 << 16);
        float hy = __uint_as_float(h01 & 0xffff0000u);
        float hz = __uint_as_float(h23 << 16);
        float hw = __uint_as_float(h23 & 0xffff0000u);
        float lx = v[t].x - hx, ly = v[t].y - hy;
        float lz = v[t].z - hz, lw = v[t].w - hw;
        asm("cvt.rn.bf16x2.f32 %0, %1, %2;" : "=r"(l01) : "f"(ly), "f"(lx));
        asm("cvt.rn.bf16x2.f32 %0, %1, %2;" : "=r"(l23) : "f"(lw), "f"(lz));
        uint32_t off = (uint32_t)((idx >> 4) * 128 + (idx & 15) * 8);
        off ^= (off >> 3) & 0x70;
        *(uint2*)(hi + off) = make_uint2(h01, h23);
        *(uint2*)(lo + off) = make_uint2(l01, l23);
    }
}

__device__ __forceinline__ float gelu_exact(float v) {
    return 0.5f * v * (1.f + erff(v * 0.70710678118654752f));
}

template<int EPI>
__global__ __launch_bounds__(256, 1) void gemm_mma(
    const float* __restrict__ A, const float* __restrict__ Bt,
    const float* __restrict__ bias, float* __restrict__ C,
    int N, int K,
    const float* __restrict__ res, const float* __restrict__ mod, int mod_off)
{
    extern __shared__ __align__(128) char smem[];
    const uint32_t sb = smem_u32(smem);
    const int tid = threadIdx.x;
    const int wid = tid >> 5, lane = tid & 31;
    const int row0 = blockIdx.y * 128, col0 = blockIdx.x * 128;
    const int wm = (wid & 1) * 64;    // warp M offset (2 warps along M)
    const int wn = (wid >> 1) * 32;   // warp N offset (4 warps along N)

    float acc[4][4][4];
    #pragma unroll
    for (int i = 0; i < 4; i++)
        #pragma unroll
        for (int j = 0; j < 4; j++)
            #pragma unroll
            for (int e = 0; e < 4; e++) acc[i][j][e] = 0.f;

    const float* Ap = A + (size_t)row0 * K;
    const float* Bp = Bt + (size_t)col0 * K;

    // per-lane ldmatrix invariants
    const int a_r = ((lane >> 3) & 1) * 8 + (lane & 7);  // A row within m16 tile
    const uint32_t a_ch = ((lane >> 4) & 1) * 16;        // A k-half byte offset
    const int b_r = (lane >> 4) * 8 + (lane & 7);        // B n-row within n16 pair
    const uint32_t b_kh = ((lane >> 3) & 1) * 16;        // B k-half byte offset
    const uint32_t kmask = (uint32_t)(lane & 7) << 4;    // SW128 xor mask

    const int NC = K >> 6;
    float4 va[8], vb[8];

    // prologue: chunk 0 -> buffer 0
    ldg_tile(Ap, K, tid, va);
    ldg_tile(Bp, K, tid, vb);
    cvt_sts(smem + STG_A_HI, smem + STG_A_LO, tid, va);
    cvt_sts(smem + STG_B_HI, smem + STG_B_LO, tid, vb);
    __syncthreads();

    for (int c2 = 0; c2 < NC; c2++) {
        const uint32_t stb = sb + (uint32_t)(c2 & 1) * STG_SIZE;
        if (c2 + 1 < NC) {
            ldg_tile(Ap + (c2 + 1) * 64, K, tid, va);
            ldg_tile(Bp + (c2 + 1) * 64, K, tid, vb);
        }
        #pragma unroll
        for (int ks = 0; ks < 4; ks++) {
            const uint32_t ka = ((uint32_t)(ks * 32) + a_ch) ^ kmask;
            const uint32_t kb = ((uint32_t)(ks * 32) + b_kh) ^ kmask;
            uint32_t ahi[4][4], alo[4][4], bhi[2][4], blo[2][4];
            #pragma unroll
            for (int mt = 0; mt < 4; mt++) {
                uint32_t rb = (uint32_t)((wm + mt * 16 + a_r) * 128);
                ldsm4(ahi[mt], stb + STG_A_HI + rb + ka);
                ldsm4(alo[mt], stb + STG_A_LO + rb + ka);
            }
            #pragma unroll
            for (int np = 0; np < 2; np++) {
                uint32_t rb = (uint32_t)((wn + np * 16 + b_r) * 128);
                ldsm4(bhi[np], stb + STG_B_HI + rb + kb);
                ldsm4(blo[np], stb + STG_B_LO + rb + kb);
            }
            #pragma unroll
            for (int mt = 0; mt < 4; mt++)
                #pragma unroll
                for (int nt = 0; nt < 4; nt++) {
                    const uint32_t b0h = bhi[nt >> 1][(nt & 1) * 2];
                    const uint32_t b1h = bhi[nt >> 1][(nt & 1) * 2 + 1];
                    const uint32_t b0l = blo[nt >> 1][(nt & 1) * 2];
                    const uint32_t b1l = blo[nt >> 1][(nt & 1) * 2 + 1];
                    mma_bf16(acc[mt][nt], ahi[mt], b0h, b1h);
                    mma_bf16(acc[mt][nt], ahi[mt], b0l, b1l);
                    mma_bf16(acc[mt][nt], alo[mt], b0h, b1h);
                }
        }
        if (c2 + 1 < NC) {
            char* st = smem + ((c2 + 1) & 1) * STG_SIZE;
            cvt_sts(st + STG_A_HI, st + STG_A_LO, tid, va);
            cvt_sts(st + STG_B_HI, st + STG_B_LO, tid, vb);
        }
        __syncthreads();
    }

    // epilogue
    #pragma unroll
    for (int mt = 0; mt < 4; mt++) {
        const int r_hi = row0 + wm + mt * 16 + (lane >> 2);
        #pragma unroll
        for (int half = 0; half < 2; half++) {
            const int row = r_hi + half * 8;
            const int batch = row >> 10;
            #pragma unroll
            for (int nt = 0; nt < 4; nt++) {
                const int col = col0 + wn + nt * 8 + (lane & 3) * 2;
                float v0 = acc[mt][nt][half * 2 + 0] + bias[col];
                float v1 = acc[mt][nt][half * 2 + 1] + bias[col + 1];
                if (EPI == 1) { v0 = gelu_exact(v0); v1 = gelu_exact(v1); }
                if (EPI == 2) {
                    const float* mp = mod + batch * MODW + mod_off + col;
                    const float* rp = res + (size_t)row * N + col;
                    v0 = rp[0] + mp[0] * v0;
                    v1 = rp[1] + mp[1] * v1;
                }
                float2 o = make_float2(v0, v1);
                *(float2*)(C + (size_t)row * N + col) = o;
            }
        }
    }
}

// ---------------------------------------------------------------------------
// attention (flash-style SIMT, known-good from R1)
// ---------------------------------------------------------------------------
__global__ __launch_bounds__(256, 1) void attn_kernel(
    const float* __restrict__ qkv, float* __restrict__ out)
{
    __shared__ __align__(16) float ks[32 * 64];
    __shared__ __align__(16) float vs[32 * 64];

    const int tid = threadIdx.x;
    const int head = blockIdx.y;
    const int batch = blockIdx.z;
    const int qrow = blockIdx.x * 256 + tid;
    const size_t token = (size_t)batch * 1024 + qrow;

    const float* qp = qkv + token * 3072 + head * 64;
    ull q2[32];
    #pragma unroll
    for (int i = 0; i < 16; i++) {
        float4 v = *(const float4*)(qp + i * 4);
        q2[2 * i]     = pack2(v.x * 0.125f, v.y * 0.125f);
        q2[2 * i + 1] = pack2(v.z * 0.125f, v.w * 0.125f);
    }
    ull o2[32];
    #pragma unroll
    for (int i = 0; i < 32; i++) o2[i] = 0ULL;
    float m = -1e30f, l = 0.f;
    float s[32];

    const float* kbase = qkv + (size_t)batch * 1024 * 3072 + 1024 + head * 64;

    for (int t = 0; t < 32; t++) {
        __syncthreads();
        #pragma unroll
        for (int p = 0; p < 2; p++) {
            int f = tid + p * 256;
            int kr = f >> 4, d4 = f & 15;
            const float* src = kbase + (size_t)(t * 32 + kr) * 3072 + d4 * 4;
            *(float4*)(ks + kr * 64 + d4 * 4) = *(const float4*)src;
            *(float4*)(vs + kr * 64 + d4 * 4) = *(const float4*)(src + 1024);
        }
        __syncthreads();

        float tmax = m;
        #pragma unroll
        for (int kr = 0; kr < 32; kr++) {
            ull accA = 0ULL, accB = 0ULL;
            const ulonglong2* kp = (const ulonglong2*)(ks + kr * 64);
            #pragma unroll
            for (int i = 0; i < 16; i++) {
                ulonglong2 kk = kp[i];
                fma2(accA, q2[2 * i],     kk.x);
                fma2(accB, q2[2 * i + 1], kk.y);
            }
            float a0, a1, b0, b1;
            unpack2(accA, a0, a1);
            unpack2(accB, b0, b1);
            s[kr] = (a0 + a1) + (b0 + b1);
            tmax = fmaxf(tmax, s[kr]);
        }

        float alpha = __expf(m - tmax);
        m = tmax;
        l *= alpha;
        ull alpha2 = pack2(alpha, alpha);
        #pragma unroll
        for (int i = 0; i < 32; i++) o2[i] = mul2(o2[i], alpha2);

        #pragma unroll
        for (int kr = 0; kr < 32; kr++) {
            float p = __expf(s[kr] - m);
            l += p;
            ull p2 = pack2(p, p);
            const ulonglong2* vp = (const ulonglong2*)(vs + kr * 64);
            #pragma unroll
            for (int i = 0; i < 16; i++) {
                ulonglong2 vv = vp[i];
                fma2(o2[2 * i],     p2, vv.x);
                fma2(o2[2 * i + 1], p2, vv.y);
            }
        }
    }

    float inv = 1.f / l;
    float* op = out + token * 1024 + head * 64;
    #pragma unroll
    for (int i = 0; i < 16; i++) {
        float a0, a1, b0, b1;
        unpack2(o2[2 * i], a0, a1);
        unpack2(o2[2 * i + 1], b0, b1);
        float4 w = make_float4(a0 * inv, a1 * inv, b0 * inv, b1 * inv);
        *(float4*)(op + i * 4) = w;
    }
}

// ---------------------------------------------------------------------------
// launch
// ---------------------------------------------------------------------------
extern "C" void kernel_launch(void* const* d_in, const int* in_sizes, int n_in,
                              void* d_out, int out_size)
{
    (void)in_sizes; (void)n_in; (void)out_size;
    const float* x      = (const float*)d_in[0];
    const float* c      = (const float*)d_in[1];
    const float* w_qkv  = (const float*)d_in[2];
    const float* b_qkv  = (const float*)d_in[3];
    const float* w_proj = (const float*)d_in[4];
    const float* b_proj = (const float*)d_in[5];
    const float* w_mlp1 = (const float*)d_in[6];
    const float* b_mlp1 = (const float*)d_in[7];
    const float* w_mlp2 = (const float*)d_in[8];
    const float* b_mlp2 = (const float*)d_in[9];
    const float* w_ada  = (const float*)d_in[10];
    const float* b_ada  = (const float*)d_in[11];
    float* out = (float*)d_out;

    float *mod, *h, *qkvb, *attn, *x1, *mlp, *wT;
    cudaGetSymbolAddress((void**)&mod,  g_mod);
    cudaGetSymbolAddress((void**)&h,    g_h);
    cudaGetSymbolAddress((void**)&qkvb, g_qkv);
    cudaGetSymbolAddress((void**)&attn, g_attn);
    cudaGetSymbolAddress((void**)&x1,   g_x1);
    cudaGetSymbolAddress((void**)&mlp,  g_mlp);
    cudaGetSymbolAddress((void**)&wT,   g_wT);

    cudaFuncSetAttribute(gemm_mma<0>, cudaFuncAttributeMaxDynamicSharedMemorySize, GEMM_SMEM);
    cudaFuncSetAttribute(gemm_mma<1>, cudaFuncAttributeMaxDynamicSharedMemorySize, GEMM_SMEM);
    cudaFuncSetAttribute(gemm_mma<2>, cudaFuncAttributeMaxDynamicSharedMemorySize, GEMM_SMEM);

    // 0) weight transposes -> K-major B operands (Bt[N][K])
    transpose_k<<<dim3(3072/32, 1024/32), dim3(32, 8)>>>(w_qkv,  wT + O_QKVT,  1024, 3072);
    transpose_k<<<dim3(1024/32, 1024/32), dim3(32, 8)>>>(w_proj, wT + O_PROJT, 1024, 1024);
    transpose_k<<<dim3(4096/32, 1024/32), dim3(32, 8)>>>(w_mlp1, wT + O_MLP1T, 1024, 4096);
    transpose_k<<<dim3(1024/32, 4096/32), dim3(32, 8)>>>(w_mlp2, wT + O_MLP2T, 4096, 1024);

    // 1) mod = silu(c) @ w_ada + b_ada
    ada_kernel<<<MODW / 256, 256>>>(c, w_ada, b_ada, mod);
    // 2) h = LN(x)*(1+g1)+be1
    ln_mod_kernel<<<TOKENS, 256>>>(x, mod, h, 0, DIM);
    // 3) qkv = h @ w_qkv + b_qkv
    gemm_mma<0><<<dim3(3072/128, TOKENS/128), 256, GEMM_SMEM>>>(
        h, wT + O_QKVT, b_qkv, qkvb, 3072, 1024, nullptr, nullptr, 0);
    // 4) attention
    attn_kernel<<<dim3(4, 16, 8), 256>>>(qkvb, attn);
    // 5) x1 = x + a1*(attn @ w_proj + b_proj)
    gemm_mma<2><<<dim3(1024/128, TOKENS/128), 256, GEMM_SMEM>>>(
        attn, wT + O_PROJT, b_proj, x1, 1024, 1024, x, mod, 2 * DIM);
    // 6) h = LN(x1)*(1+g2)+be2
    ln_mod_kernel<<<TOKENS, 256>>>(x1, mod, h, 3 * DIM, 4 * DIM);
    // 7) mlp = gelu(h @ w_mlp1 + b_mlp1)
    gemm_mma<1><<<dim3(4096/128, TOKENS/128), 256, GEMM_SMEM>>>(
        h, wT + O_MLP1T, b_mlp1, mlp, 4096, 1024, nullptr, nullptr, 0);
    // 8) out = x1 + a2*(mlp @ w_mlp2 + b_mlp2)
    gemm_mma<2><<<dim3(1024/128, TOKENS/128), 256, GEMM_SMEM>>>(
        mlp, wT + O_MLP2T, b_mlp2, out, 1024, 4096, x1, mod, 5 * DIM);
}

// round 5
// speedup vs baseline: 3.2731x; 1.6515x over previous
#include <cuda_runtime.h>
#include <cuda_bf16.h>
#include <math.h>
#include <cstdint>

#define DIM 1024
#define MODW 6144
#define TOKENS 8192   // B(8) * N(1024)

// ---------------------------------------------------------------------------
// helpers
// ---------------------------------------------------------------------------
__device__ __forceinline__ uint32_t smem_u32(const void* p) {
    uint32_t a;
    asm("{ .reg .u64 t; cvta.to.shared.u64 t, %1; cvt.u32.u64 %0, t; }"
        : "=r"(a) : "l"(p));
    return a;
}
__device__ __forceinline__ void ldsm4(uint32_t r[4], uint32_t addr) {
    asm volatile("ldmatrix.sync.aligned.m8n8.x4.shared.b16 {%0,%1,%2,%3}, [%4];"
        : "=r"(r[0]), "=r"(r[1]), "=r"(r[2]), "=r"(r[3]) : "r"(addr));
}
__device__ __forceinline__ void ldsm4t(uint32_t r[4], uint32_t addr) {
    asm volatile("ldmatrix.sync.aligned.m8n8.x4.trans.shared.b16 {%0,%1,%2,%3}, [%4];"
        : "=r"(r[0]), "=r"(r[1]), "=r"(r[2]), "=r"(r[3]) : "r"(addr));
}
__device__ __forceinline__ void mma_bf16(float c[4], const uint32_t a[4],
                                         uint32_t b0, uint32_t b1) {
    asm volatile(
        "mma.sync.aligned.m16n8k16.row.col.f32.bf16.bf16.f32 "
        "{%0,%1,%2,%3}, {%4,%5,%6,%7}, {%8,%9}, {%0,%1,%2,%3};"
        : "+f"(c[0]), "+f"(c[1]), "+f"(c[2]), "+f"(c[3])
        : "r"(a[0]), "r"(a[1]), "r"(a[2]), "r"(a[3]), "r"(b0), "r"(b1));
}
__device__ __forceinline__ void cpa16(uint32_t dst, const void* src) {
    asm volatile("cp.async.cg.shared.global [%0], [%1], 16;" :: "r"(dst), "l"(src));
}
#define CP_COMMIT asm volatile("cp.async.commit_group;" ::: "memory")
#define CP_WAIT1  asm volatile("cp.async.wait_group 1;"  ::: "memory")

// split v0,v1 -> bf16x2 hi plane word + lo plane word
__device__ __forceinline__ void split_pack(float v0, float v1,
                                           uint32_t& hi, uint32_t& lo) {
    asm("cvt.rn.bf16x2.f32 %0, %1, %2;" : "=r"(hi) : "f"(v1), "f"(v0));
    float h0 = __uint_as_float(hi << 16);
    float h1 = __uint_as_float(hi & 0xffff0000u);
    asm("cvt.rn.bf16x2.f32 %0, %1, %2;" : "=r"(lo) : "f"(v1 - h1), "f"(v0 - h0));
}
__device__ __forceinline__ void split_pack4(const float4& v,
        uint32_t& h01, uint32_t& h23, uint32_t& l01, uint32_t& l23) {
    split_pack(v.x, v.y, h01, l01);
    split_pack(v.z, v.w, h23, l23);
}
__device__ __forceinline__ float gelu_exact(float v) {
    return 0.5f * v * (1.f + erff(v * 0.70710678118654752f));
}

// ---------------------------------------------------------------------------
// scratch (no allocations allowed)
// ---------------------------------------------------------------------------
__device__ __align__(16) float    g_mod[8 * MODW];
__device__ __align__(16) uint16_t g_h_hi[(size_t)TOKENS * DIM];
__device__ __align__(16) uint16_t g_h_lo[(size_t)TOKENS * DIM];
__device__ __align__(16) float    g_qkv[(size_t)TOKENS * 3 * DIM];
__device__ __align__(16) uint16_t g_at_hi[(size_t)TOKENS * DIM];
__device__ __align__(16) uint16_t g_at_lo[(size_t)TOKENS * DIM];
__device__ __align__(16) float    g_x1[(size_t)TOKENS * DIM];
__device__ __align__(16) uint16_t g_mlp_hi[(size_t)TOKENS * 4 * DIM];
__device__ __align__(16) uint16_t g_mlp_lo[(size_t)TOKENS * 4 * DIM];
__device__ __align__(16) uint16_t g_w_hi[12 * 1024 * 1024 + 65536];
__device__ __align__(16) uint16_t g_w_lo[12 * 1024 * 1024 + 65536];
#define O_QKVT 0
#define O_PROJT 3145728
#define O_MLP1T 4194304
#define O_MLP2T 8388608

// ---------------------------------------------------------------------------
// weight transpose + bf16 split: src [R][C] fp32 -> dst planes [C][R] bf16
// ---------------------------------------------------------------------------
__global__ __launch_bounds__(256) void wsplitT(
    const float* __restrict__ s, uint16_t* __restrict__ dhi,
    uint16_t* __restrict__ dlo, int R, int C)
{
    __shared__ float t[32][33];
    const int bx = blockIdx.x * 32;
    const int by = blockIdx.y * 32;
    const int x = threadIdx.x, y = threadIdx.y;
    #pragma unroll
    for (int i = 0; i < 32; i += 8)
        t[y + i][x] = s[(size_t)(by + y + i) * C + bx + x];
    __syncthreads();
    #pragma unroll
    for (int i = 0; i < 32; i += 8) {
        float v = t[x][y + i];
        uint32_t hb, lb;
        asm("cvt.rn.bf16x2.f32 %0, %1, %2;" : "=r"(hb) : "f"(0.f), "f"(v));
        float hf = __uint_as_float(hb << 16);
        asm("cvt.rn.bf16x2.f32 %0, %1, %2;" : "=r"(lb) : "f"(0.f), "f"(v - hf));
        size_t o = (size_t)(bx + y + i) * R + by + x;
        dhi[o] = (uint16_t)(hb & 0xffffu);
        dlo[o] = (uint16_t)(lb & 0xffffu);
    }
}

// ---------------------------------------------------------------------------
// adaLN modulation GEMM (M=8), 4-way k-split + smem reduce
// ---------------------------------------------------------------------------
__global__ __launch_bounds__(256) void ada_kernel(
    const float* __restrict__ c, const float* __restrict__ w,
    const float* __restrict__ bias, float* __restrict__ mod)
{
    __shared__ float sc[8 * DIM];
    __shared__ float red[4][8][64];
    const int tid = threadIdx.x;
    for (int i = tid; i < 8 * DIM; i += 256) {
        float v = c[i];
        sc[i] = v / (1.f + __expf(-v));
    }
    __syncthreads();
    const int cidx = tid & 63, kq = tid >> 6;
    const int col = blockIdx.x * 64 + cidx;
    float acc[8];
    #pragma unroll
    for (int b = 0; b < 8; b++) acc[b] = 0.f;
    const int k0 = kq * 256;
    for (int k = k0; k < k0 + 256; k++) {
        float wv = w[(size_t)k * MODW + col];
        #pragma unroll
        for (int b = 0; b < 8; b++) acc[b] = fmaf(sc[b * DIM + k], wv, acc[b]);
    }
    #pragma unroll
    for (int b = 0; b < 8; b++) red[kq][b][cidx] = acc[b];
    __syncthreads();
    if (kq == 0) {
        float bv = bias[col];
        #pragma unroll
        for (int b = 0; b < 8; b++)
            mod[b * MODW + col] =
                red[0][b][cidx] + red[1][b][cidx] + red[2][b][cidx] +
                red[3][b][cidx] + bv;
    }
}

// ---------------------------------------------------------------------------
// LayerNorm + modulate -> bf16 hi/lo planes
// ---------------------------------------------------------------------------
__global__ __launch_bounds__(256) void ln_mod_kernel(
    const float* __restrict__ x, const float* __restrict__ mod,
    uint16_t* __restrict__ hhi, uint16_t* __restrict__ hlo,
    int g_off, int b_off)
{
    __shared__ float s_sum[8], s_sq[8], s_stats[2];
    const int token = blockIdx.x;
    const int batch = token >> 10;
    const int tid = threadIdx.x;

    const float4* xp = (const float4*)(x + (size_t)token * DIM);
    float4 v = xp[tid];
    float sum = v.x + v.y + v.z + v.w;
    float sq  = v.x*v.x + v.y*v.y + v.z*v.z + v.w*v.w;
    #pragma unroll
    for (int o = 16; o > 0; o >>= 1) {
        sum += __shfl_xor_sync(0xffffffffu, sum, o);
        sq  += __shfl_xor_sync(0xffffffffu, sq,  o);
    }
    if ((tid & 31) == 0) { s_sum[tid >> 5] = sum; s_sq[tid >> 5] = sq; }
    __syncthreads();
    if (tid < 32) {
        float a = (tid < 8) ? s_sum[tid] : 0.f;
        float b = (tid < 8) ? s_sq[tid]  : 0.f;
        #pragma unroll
        for (int o = 4; o > 0; o >>= 1) {
            a += __shfl_xor_sync(0xffffffffu, a, o);
            b += __shfl_xor_sync(0xffffffffu, b, o);
        }
        if (tid == 0) {
            float mu = a * (1.f / DIM);
            float var = b * (1.f / DIM) - mu * mu;
            s_stats[0] = mu;
            s_stats[1] = rsqrtf(var + 1e-6f);
        }
    }
    __syncthreads();
    const float mu = s_stats[0], rstd = s_stats[1];
    const float4* gp = (const float4*)(mod + batch * MODW + g_off);
    const float4* bp = (const float4*)(mod + batch * MODW + b_off);
    float4 g = gp[tid], be = bp[tid], o;
    o.x = (v.x - mu) * rstd * (1.f + g.x) + be.x;
    o.y = (v.y - mu) * rstd * (1.f + g.y) + be.y;
    o.z = (v.z - mu) * rstd * (1.f + g.z) + be.z;
    o.w = (v.w - mu) * rstd * (1.f + g.w) + be.w;
    uint32_t h01, h23, l01, l23;
    split_pack4(o, h01, h23, l01, l23);
    size_t off = (size_t)token * DIM + tid * 4;
    *(uint2*)(hhi + off) = make_uint2(h01, h23);
    *(uint2*)(hlo + off) = make_uint2(l01, l23);
}

// ---------------------------------------------------------------------------
// GEMM: C[M,N] = A @ Bt^T from pre-split bf16 planes, 3-MMA fp32 emulation,
// cp.async 3-stage pipeline. CTA tile 128x128, k-chunk 64.
// ---------------------------------------------------------------------------
#define STG_A_HI 0
#define STG_A_LO 16384
#define STG_B_HI 32768
#define STG_B_LO 49152
#define STG_SIZE 65536
#define GEMM_SMEM (3 * STG_SIZE)   // 196608

__device__ __forceinline__ void fill_plane(
    uint32_t dst, const uint8_t* __restrict__ src, size_t rs, int tid)
{
    #pragma unroll
    for (int q = 0; q < 4; q++) {
        int idx = q * 256 + tid;
        int row = idx >> 3, c16 = idx & 7;
        uint32_t off = (uint32_t)(row * 128 + c16 * 16);
        off ^= (off >> 3) & 0x70;
        cpa16(dst + off, src + (size_t)row * rs + c16 * 16);
    }
}

template<int EPI>
__global__ __launch_bounds__(256, 1) void gemm_mma(
    const uint16_t* __restrict__ Ahi, const uint16_t* __restrict__ Alo,
    const uint16_t* __restrict__ Bhi, const uint16_t* __restrict__ Blo,
    const float* __restrict__ bias,
    float* __restrict__ C, uint16_t* __restrict__ Chi, uint16_t* __restrict__ Clo,
    int N, int K,
    const float* __restrict__ res, const float* __restrict__ mod, int mod_off)
{
    extern __shared__ __align__(128) char smem[];
    const uint32_t sb = smem_u32(smem);
    const int tid = threadIdx.x;
    const int wid = tid >> 5, lane = tid & 31;
    const int row0 = blockIdx.y * 128, col0 = blockIdx.x * 128;
    const int wm = (wid & 1) * 64;
    const int wn = (wid >> 1) * 32;

    float acc[4][4][4];
    #pragma unroll
    for (int i = 0; i < 4; i++)
        #pragma unroll
        for (int j = 0; j < 4; j++)
            #pragma unroll
            for (int e = 0; e < 4; e++) acc[i][j][e] = 0.f;

    const size_t rs = (size_t)K * 2;
    const uint8_t* pa_hi = (const uint8_t*)Ahi + (size_t)row0 * rs;
    const uint8_t* pa_lo = (const uint8_t*)Alo + (size_t)row0 * rs;
    const uint8_t* pb_hi = (const uint8_t*)Bhi + (size_t)col0 * rs;
    const uint8_t* pb_lo = (const uint8_t*)Blo + (size_t)col0 * rs;

    const int a_r = ((lane >> 3) & 1) * 8 + (lane & 7);
    const uint32_t a_ch = ((lane >> 4) & 1) * 16;
    const int b_r = (lane >> 4) * 8 + (lane & 7);
    const uint32_t b_kh = ((lane >> 3) & 1) * 16;
    const uint32_t kmask = (uint32_t)(lane & 7) << 4;

    const int NC = K >> 6;

    {
        uint32_t st = sb;
        fill_plane(st + STG_A_HI, pa_hi, rs, tid);
        fill_plane(st + STG_A_LO, pa_lo, rs, tid);
        fill_plane(st + STG_B_HI, pb_hi, rs, tid);
        fill_plane(st + STG_B_LO, pb_lo, rs, tid);
    }
    CP_COMMIT;
    if (NC > 1) {
        uint32_t st = sb + STG_SIZE;
        fill_plane(st + STG_A_HI, pa_hi + 128, rs, tid);
        fill_plane(st + STG_A_LO, pa_lo + 128, rs, tid);
        fill_plane(st + STG_B_HI, pb_hi + 128, rs, tid);
        fill_plane(st + STG_B_LO, pb_lo + 128, rs, tid);
    }
    CP_COMMIT;

    int sidx = 0;
    for (int c = 0; c < NC; c++) {
        CP_WAIT1;
        __syncthreads();
        if (c + 2 < NC) {
            int s2 = sidx + 2; if (s2 >= 3) s2 -= 3;
            uint32_t st = sb + (uint32_t)s2 * STG_SIZE;
            const size_t ko = (size_t)(c + 2) * 128;
            fill_plane(st + STG_A_HI, pa_hi + ko, rs, tid);
            fill_plane(st + STG_A_LO, pa_lo + ko, rs, tid);
            fill_plane(st + STG_B_HI, pb_hi + ko, rs, tid);
            fill_plane(st + STG_B_LO, pb_lo + ko, rs, tid);
        }
        CP_COMMIT;

        const uint32_t stb = sb + (uint32_t)sidx * STG_SIZE;
        #pragma unroll
        for (int ks = 0; ks < 4; ks++) {
            const uint32_t ka = ((uint32_t)(ks * 32) + a_ch) ^ kmask;
            const uint32_t kb = ((uint32_t)(ks * 32) + b_kh) ^ kmask;
            uint32_t ahi[4][4], alo[4][4], bhi[2][4], blo[2][4];
            #pragma unroll
            for (int mt = 0; mt < 4; mt++) {
                uint32_t rb = (uint32_t)((wm + mt * 16 + a_r) * 128);
                ldsm4(ahi[mt], stb + STG_A_HI + rb + ka);
                ldsm4(alo[mt], stb + STG_A_LO + rb + ka);
            }
            #pragma unroll
            for (int np = 0; np < 2; np++) {
                uint32_t rb = (uint32_t)((wn + np * 16 + b_r) * 128);
                ldsm4(bhi[np], stb + STG_B_HI + rb + kb);
                ldsm4(blo[np], stb + STG_B_LO + rb + kb);
            }
            #pragma unroll
            for (int mt = 0; mt < 4; mt++)
                #pragma unroll
                for (int nt = 0; nt < 4; nt++) {
                    const uint32_t b0h = bhi[nt >> 1][(nt & 1) * 2];
                    const uint32_t b1h = bhi[nt >> 1][(nt & 1) * 2 + 1];
                    const uint32_t b0l = blo[nt >> 1][(nt & 1) * 2];
                    const uint32_t b1l = blo[nt >> 1][(nt & 1) * 2 + 1];
                    mma_bf16(acc[mt][nt], ahi[mt], b0h, b1h);
                    mma_bf16(acc[mt][nt], ahi[mt], b0l, b1l);
                    mma_bf16(acc[mt][nt], alo[mt], b0h, b1h);
                }
        }
        if (++sidx == 3) sidx = 0;
    }

    #pragma unroll
    for (int mt = 0; mt < 4; mt++) {
        const int r_hi = row0 + wm + mt * 16 + (lane >> 2);
        #pragma unroll
        for (int half = 0; half < 2; half++) {
            const int row = r_hi + half * 8;
            const int batch = row >> 10;
            #pragma unroll
            for (int nt = 0; nt < 4; nt++) {
                const int col = col0 + wn + nt * 8 + (lane & 3) * 2;
                float v0 = acc[mt][nt][half * 2 + 0] + bias[col];
                float v1 = acc[mt][nt][half * 2 + 1] + bias[col + 1];
                if (EPI == 1) {
                    v0 = gelu_exact(v0); v1 = gelu_exact(v1);
                    uint32_t hw, lw;
                    split_pack(v0, v1, hw, lw);
                    *(uint32_t*)(Chi + (size_t)row * N + col) = hw;
                    *(uint32_t*)(Clo + (size_t)row * N + col) = lw;
                } else {
                    if (EPI == 2) {
                        const float* mp = mod + batch * MODW + mod_off + col;
                        const float* rp = res + (size_t)row * N + col;
                        v0 = rp[0] + mp[0] * v0;
                        v1 = rp[1] + mp[1] * v1;
                    }
                    *(float2*)(C + (size_t)row * N + col) = make_float2(v0, v1);
                }
            }
        }
    }
}

// ---------------------------------------------------------------------------
// attention: FA2-style, split-bf16 3-MMA for QK^T and PV.
// ---------------------------------------------------------------------------
#define A_KHI 0
#define A_KLO 8192
#define A_VHI 16384
#define A_VLO 24576
#define A_STG 32768
#define A_QHI 65536
#define A_QLO 81920
#define ATT_SMEM 98304

__global__ __launch_bounds__(256, 1) void attn_mma(
    const float* __restrict__ qkv,
    uint16_t* __restrict__ ohi, uint16_t* __restrict__ olo)
{
    extern __shared__ __align__(128) char smem[];
    const uint32_t sb = smem_u32(smem);
    const int tid = threadIdx.x;
    const int wid = tid >> 5, lane = tid & 31;
    const int qt = blockIdx.x, head = blockIdx.y, batch = blockIdx.z;

    const float* qbase = qkv + (size_t)batch * 1024 * 3072 + head * 64;
    const float* kvbase = qbase + 1024;

    // ---- stage Q (scaled by 1/8) into planes: each float4 -> 8 bytes/plane
    #pragma unroll
    for (int p = 0; p < 8; p++) {
        int idx = p * 256 + tid;
        int row = idx >> 4, c4 = idx & 15;
        float4 v = *(const float4*)(qbase + (size_t)(qt * 128 + row) * 3072 + c4 * 4);
        v.x *= 0.125f; v.y *= 0.125f; v.z *= 0.125f; v.w *= 0.125f;
        uint32_t h01, h23, l01, l23;
        split_pack4(v, h01, h23, l01, l23);
        uint32_t off = (uint32_t)(row * 128 + c4 * 8);
        off ^= (off >> 3) & 0x70;
        *(uint2*)(smem + A_QHI + off) = make_uint2(h01, h23);
        *(uint2*)(smem + A_QLO + off) = make_uint2(l01, l23);
    }

    // ---- prefetch KV tile 0
    float4 kv[8];
    #pragma unroll
    for (int p = 0; p < 4; p++) {
        int idx = p * 256 + tid;
        kv[p] = *(const float4*)(kvbase + (size_t)(idx >> 4) * 3072 + (idx & 15) * 4);
        kv[4 + p] = *(const float4*)(kvbase + 1024 + (size_t)(idx >> 4) * 3072 + (idx & 15) * 4);
    }
    __syncthreads();

    const int a_r = ((lane >> 3) & 1) * 8 + (lane & 7);
    const uint32_t a_ch = ((lane >> 4) & 1) * 16;
    const int b_r = (lane >> 4) * 8 + (lane & 7);
    const uint32_t b_kh = ((lane >> 3) & 1) * 16;
    const uint32_t kmask = (uint32_t)(lane & 7) << 4;
    const int wq = wid * 16;

    uint32_t qh[4][4], ql[4][4];
    #pragma unroll
    for (int ks = 0; ks < 4; ks++) {
        uint32_t ka = ((uint32_t)(ks * 32) + a_ch) ^ kmask;
        uint32_t rb = (uint32_t)((wq + a_r) * 128);
        ldsm4(qh[ks], sb + A_QHI + rb + ka);
        ldsm4(ql[ks], sb + A_QLO + rb + ka);
    }

    // ---- store KV tile 0 into stage 0 (8 bytes per float4 per plane)
    {
        char* st = smem;
        #pragma unroll
        for (int m = 0; m < 2; m++)
            #pragma unroll
            for (int p = 0; p < 4; p++) {
                int idx = p * 256 + tid;
                int row = idx >> 4, c4 = idx & 15;
                uint32_t h01, h23, l01, l23;
                split_pack4(kv[m * 4 + p], h01, h23, l01, l23);
                uint32_t off = (uint32_t)(row * 128 + c4 * 8);
                off ^= (off >> 3) & 0x70;
                *(uint2*)(st + (m ? A_VHI : A_KHI) + off) = make_uint2(h01, h23);
                *(uint2*)(st + (m ? A_VLO : A_KLO) + off) = make_uint2(l01, l23);
            }
    }
    __syncthreads();

    const int v_row = lane & 15;
    const uint32_t v_colb = (uint32_t)((lane >> 4) * 16);

    float m0 = -1e30f, m1 = -1e30f, l0 = 0.f, l1 = 0.f;
    float o[8][4];
    #pragma unroll
    for (int i = 0; i < 8; i++)
        #pragma unroll
        for (int e = 0; e < 4; e++) o[i][e] = 0.f;

    for (int t = 0; t < 16; t++) {
        if (t < 15) {
            const float* kb = kvbase + (size_t)(t + 1) * 64 * 3072;
            #pragma unroll
            for (int p = 0; p < 4; p++) {
                int idx = p * 256 + tid;
                kv[p] = *(const float4*)(kb + (size_t)(idx >> 4) * 3072 + (idx & 15) * 4);
                kv[4 + p] = *(const float4*)(kb + 1024 + (size_t)(idx >> 4) * 3072 + (idx & 15) * 4);
            }
        }
        const uint32_t stb = sb + (uint32_t)(t & 1) * A_STG;

        // ---- S = Q K^T
        float s[8][4];
        #pragma unroll
        for (int i = 0; i < 8; i++)
            #pragma unroll
            for (int e = 0; e < 4; e++) s[i][e] = 0.f;
        #pragma unroll
        for (int ks = 0; ks < 4; ks++) {
            const uint32_t kb2 = ((uint32_t)(ks * 32) + b_kh) ^ kmask;
            #pragma unroll
            for (int np = 0; np < 4; np++) {
                uint32_t rb = (uint32_t)((np * 16 + b_r) * 128);
                uint32_t kh[4], kl[4];
                ldsm4(kh, stb + A_KHI + rb + kb2);
                ldsm4(kl, stb + A_KLO + rb + kb2);
                mma_bf16(s[2 * np],     qh[ks], kh[0], kh[1]);
                mma_bf16(s[2 * np],     qh[ks], kl[0], kl[1]);
                mma_bf16(s[2 * np],     ql[ks], kh[0], kh[1]);
                mma_bf16(s[2 * np + 1], qh[ks], kh[2], kh[3]);
                mma_bf16(s[2 * np + 1], qh[ks], kl[2], kl[3]);
                mma_bf16(s[2 * np + 1], ql[ks], kh[2], kh[3]);
            }
        }

        // ---- online softmax
        float mx0 = -1e30f, mx1 = -1e30f;
        #pragma unroll
        for (int i = 0; i < 8; i++) {
            mx0 = fmaxf(mx0, fmaxf(s[i][0], s[i][1]));
            mx1 = fmaxf(mx1, fmaxf(s[i][2], s[i][3]));
        }
        mx0 = fmaxf(mx0, __shfl_xor_sync(0xffffffffu, mx0, 1));
        mx0 = fmaxf(mx0, __shfl_xor_sync(0xffffffffu, mx0, 2));
        mx1 = fmaxf(mx1, __shfl_xor_sync(0xffffffffu, mx1, 1));
        mx1 = fmaxf(mx1, __shfl_xor_sync(0xffffffffu, mx1, 2));
        const float mn0 = fmaxf(m0, mx0), mn1 = fmaxf(m1, mx1);
        const float al0 = __expf(m0 - mn0), al1 = __expf(m1 - mn1);
        m0 = mn0; m1 = mn1;

        float ps0 = 0.f, ps1 = 0.f;
        uint32_t pf_hi[4][4], pf_lo[4][4];
        #pragma unroll
        for (int i = 0; i < 8; i++) {
            float p0 = __expf(s[i][0] - m0);
            float p1 = __expf(s[i][1] - m0);
            float p2 = __expf(s[i][2] - m1);
            float p3 = __expf(s[i][3] - m1);
            ps0 += p0 + p1; ps1 += p2 + p3;
            const int j = i >> 1, q = (i & 1) * 2;
            split_pack(p0, p1, pf_hi[j][q],     pf_lo[j][q]);
            split_pack(p2, p3, pf_hi[j][q + 1], pf_lo[j][q + 1]);
        }
        ps0 += __shfl_xor_sync(0xffffffffu, ps0, 1);
        ps0 += __shfl_xor_sync(0xffffffffu, ps0, 2);
        ps1 += __shfl_xor_sync(0xffffffffu, ps1, 1);
        ps1 += __shfl_xor_sync(0xffffffffu, ps1, 2);
        l0 = l0 * al0 + ps0;
        l1 = l1 * al1 + ps1;
        #pragma unroll
        for (int i = 0; i < 8; i++) {
            o[i][0] *= al0; o[i][1] *= al0;
            o[i][2] *= al1; o[i][3] *= al1;
        }

        // ---- O += P V
        #pragma unroll
        for (int j = 0; j < 4; j++) {
            #pragma unroll
            for (int tp = 0; tp < 4; tp++) {
                uint32_t off = (uint32_t)((j * 16 + v_row) * 128 + tp * 32) + v_colb;
                off ^= (off >> 3) & 0x70;
                uint32_t vh[4], vl[4];
                ldsm4t(vh, stb + A_VHI + off);
                ldsm4t(vl, stb + A_VLO + off);
                mma_bf16(o[2 * tp],     pf_hi[j], vh[0], vh[1]);
                mma_bf16(o[2 * tp],     pf_hi[j], vl[0], vl[1]);
                mma_bf16(o[2 * tp],     pf_lo[j], vh[0], vh[1]);
                mma_bf16(o[2 * tp + 1], pf_hi[j], vh[2], vh[3]);
                mma_bf16(o[2 * tp + 1], pf_hi[j], vl[2], vl[3]);
                mma_bf16(o[2 * tp + 1], pf_lo[j], vh[2], vh[3]);
            }
        }

        // ---- store next tile into other stage
        if (t < 15) {
            char* st = smem + ((t + 1) & 1) * A_STG;
            #pragma unroll
            for (int m = 0; m < 2; m++)
                #pragma unroll
                for (int p = 0; p < 4; p++) {
                    int idx = p * 256 + tid;
                    int row = idx >> 4, c4 = idx & 15;
                    uint32_t h01, h23, l01, l23;
                    split_pack4(kv[m * 4 + p], h01, h23, l01, l23);
                    uint32_t off = (uint32_t)(row * 128 + c4 * 8);
                    off ^= (off >> 3) & 0x70;
                    *(uint2*)(st + (m ? A_VHI : A_KHI) + off) = make_uint2(h01, h23);
                    *(uint2*)(st + (m ? A_VLO : A_KLO) + off) = make_uint2(l01, l23);
                }
        }
        __syncthreads();
    }

    const float inv0 = 1.f / l0, inv1 = 1.f / l1;
    const int rowg = batch * 1024 + qt * 128 + wq + (lane >> 2);
    const int colb = head * 64 + (lane & 3) * 2;
    #pragma unroll
    for (int i = 0; i < 8; i++) {
        const int col = colb + i * 8;
        uint32_t hw, lw;
        split_pack(o[i][0] * inv0, o[i][1] * inv0, hw, lw);
        *(uint32_t*)(ohi + (size_t)rowg * 1024 + col) = hw;
        *(uint32_t*)(olo + (size_t)rowg * 1024 + col) = lw;
        split_pack(o[i][2] * inv1, o[i][3] * inv1, hw, lw);
        *(uint32_t*)(ohi + (size_t)(rowg + 8) * 1024 + col) = hw;
        *(uint32_t*)(olo + (size_t)(rowg + 8) * 1024 + col) = lw;
    }
}

// ---------------------------------------------------------------------------
// launch
// ---------------------------------------------------------------------------
extern "C" void kernel_launch(void* const* d_in, const int* in_sizes, int n_in,
                              void* d_out, int out_size)
{
    (void)in_sizes; (void)n_in; (void)out_size;
    const float* x      = (const float*)d_in[0];
    const float* c      = (const float*)d_in[1];
    const float* w_qkv  = (const float*)d_in[2];
    const float* b_qkv  = (const float*)d_in[3];
    const float* w_proj = (const float*)d_in[4];
    const float* b_proj = (const float*)d_in[5];
    const float* w_mlp1 = (const float*)d_in[6];
    const float* b_mlp1 = (const float*)d_in[7];
    const float* w_mlp2 = (const float*)d_in[8];
    const float* b_mlp2 = (const float*)d_in[9];
    const float* w_ada  = (const float*)d_in[10];
    const float* b_ada  = (const float*)d_in[11];
    float* out = (float*)d_out;

    float *mod, *qkvb, *x1;
    uint16_t *hhi, *hlo, *athi, *atlo, *mhi, *mlo, *whi, *wlo;
    cudaGetSymbolAddress((void**)&mod,  g_mod);
    cudaGetSymbolAddress((void**)&hhi,  g_h_hi);
    cudaGetSymbolAddress((void**)&hlo,  g_h_lo);
    cudaGetSymbolAddress((void**)&qkvb, g_qkv);
    cudaGetSymbolAddress((void**)&athi, g_at_hi);
    cudaGetSymbolAddress((void**)&atlo, g_at_lo);
    cudaGetSymbolAddress((void**)&x1,   g_x1);
    cudaGetSymbolAddress((void**)&mhi,  g_mlp_hi);
    cudaGetSymbolAddress((void**)&mlo,  g_mlp_lo);
    cudaGetSymbolAddress((void**)&whi,  g_w_hi);
    cudaGetSymbolAddress((void**)&wlo,  g_w_lo);

    cudaFuncSetAttribute(gemm_mma<0>, cudaFuncAttributeMaxDynamicSharedMemorySize, GEMM_SMEM);
    cudaFuncSetAttribute(gemm_mma<1>, cudaFuncAttributeMaxDynamicSharedMemorySize, GEMM_SMEM);
    cudaFuncSetAttribute(gemm_mma<2>, cudaFuncAttributeMaxDynamicSharedMemorySize, GEMM_SMEM);
    cudaFuncSetAttribute(attn_mma,    cudaFuncAttributeMaxDynamicSharedMemorySize, ATT_SMEM);

    wsplitT<<<dim3(3072/32, 1024/32), dim3(32, 8)>>>(w_qkv,  whi + O_QKVT,  wlo + O_QKVT,  1024, 3072);
    wsplitT<<<dim3(1024/32, 1024/32), dim3(32, 8)>>>(w_proj, whi + O_PROJT, wlo + O_PROJT, 1024, 1024);
    wsplitT<<<dim3(4096/32, 1024/32), dim3(32, 8)>>>(w_mlp1, whi + O_MLP1T, wlo + O_MLP1T, 1024, 4096);
    wsplitT<<<dim3(1024/32, 4096/32), dim3(32, 8)>>>(w_mlp2, whi + O_MLP2T, wlo + O_MLP2T, 4096, 1024);

    ada_kernel<<<MODW / 64, 256>>>(c, w_ada, b_ada, mod);
    ln_mod_kernel<<<TOKENS, 256>>>(x, mod, hhi, hlo, 0, DIM);
    gemm_mma<0><<<dim3(3072/128, TOKENS/128), 256, GEMM_SMEM>>>(
        hhi, hlo, whi + O_QKVT, wlo + O_QKVT, b_qkv,
        qkvb, nullptr, nullptr, 3072, 1024, nullptr, nullptr, 0);
    attn_mma<<<dim3(8, 16, 8), 256, ATT_SMEM>>>(qkvb, athi, atlo);
    gemm_mma<2><<<dim3(1024/128, TOKENS/128), 256, GEMM_SMEM>>>(
        athi, atlo, whi + O_PROJT, wlo + O_PROJT, b_proj,
        x1, nullptr, nullptr, 1024, 1024, x, mod, 2 * DIM);
    ln_mod_kernel<<<TOKENS, 256>>>(x1, mod, hhi, hlo, 3 * DIM, 4 * DIM);
    gemm_mma<1><<<dim3(4096/128, TOKENS/128), 256, GEMM_SMEM>>>(
        hhi, hlo, whi + O_MLP1T, wlo + O_MLP1T, b_mlp1,
        nullptr, mhi, mlo, 4096, 1024, nullptr, nullptr, 0);
    gemm_mma<2><<<dim3(1024/128, TOKENS/128), 256, GEMM_SMEM>>>(
        mhi, mlo, whi + O_MLP2T, wlo + O_MLP2T, b_mlp2,
        out, nullptr, nullptr, 1024, 4096, x1, mod, 5 * DIM);
}